// round 3
// baseline (speedup 1.0000x reference)
#include <cuda_runtime.h>
#include <math.h>

#define NNODES 20000
#define NEDGES 640000
#define NSZ 128
#define ESZ 20
#define CUTF 5.0f

// scratch
__device__ float g_so[NNODES * 384];
__device__ int g_hist[NNODES + 1];
__device__ int g_row[NNODES + 1];
__device__ int g_off[NNODES];
__device__ int g_perm[NEDGES];

typedef unsigned long long u64;

// ---------------------------------------------------------------------------
__device__ __forceinline__ void fma2(u64& d, u64 a, u64 b) {
    asm("fma.rn.f32x2 %0, %1, %2, %0;" : "+l"(d) : "l"(a), "l"(b));
}
__device__ __forceinline__ u64 pack2(float x) {
    u64 r; asm("mov.b64 %0, {%1, %1};" : "=l"(r) : "f"(x)); return r;
}
__device__ __forceinline__ float2 unpack2(u64 a) {
    float2 f; asm("mov.b64 {%0, %1}, %2;" : "=f"(f.x), "=f"(f.y) : "l"(a));
    return f;
}
__device__ __forceinline__ float4 f4_fma_s(float a, float4 w, float4 c) {
    c.x = fmaf(a, w.x, c.x); c.y = fmaf(a, w.y, c.y);
    c.z = fmaf(a, w.z, c.z); c.w = fmaf(a, w.w, c.w);
    return c;
}
__device__ __forceinline__ float4 f4_mul(float4 a, float4 b) {
    return make_float4(a.x*b.x, a.y*b.y, a.z*b.z, a.w*b.w);
}
// acc += xv * g
__device__ __forceinline__ void f4_acc_mul(float4& acc, float4 xv, float4 g) {
    acc.x = fmaf(xv.x, g.x, acc.x); acc.y = fmaf(xv.y, g.y, acc.y);
    acc.z = fmaf(xv.z, g.z, acc.z); acc.w = fmaf(xv.w, g.w, acc.w);
}
// acc += s * f
__device__ __forceinline__ void f4_acc_s(float4& acc, float s, float4 f) {
    acc.x = fmaf(s, f.x, acc.x); acc.y = fmaf(s, f.y, acc.y);
    acc.z = fmaf(s, f.z, acc.z); acc.w = fmaf(s, f.w, acc.w);
}

// ---------------------------------------------------------------------------
// CSR build kernels
// ---------------------------------------------------------------------------
__global__ void csr_zero() {
    int i = blockIdx.x * 256 + threadIdx.x;
    if (i <= NNODES) g_hist[i] = 0;
}
__global__ void csr_hist(const int* __restrict__ edges) {
    int i = blockIdx.x * 256 + threadIdx.x;
    if (i < NEDGES) atomicAdd(&g_hist[edges[2 * i + 1]], 1);
}
__global__ void __launch_bounds__(1024) csr_scan() {
    __shared__ int s[1024];
    const int t = threadIdx.x;
    const int C = 20;                        // 1024*20 >= 20000
    const int base = t * C;
    int sum = 0;
    #pragma unroll
    for (int j = 0; j < C; j++) {
        int idx = base + j;
        if (idx < NNODES) sum += g_hist[idx];
    }
    s[t] = sum;
    __syncthreads();
    for (int off = 1; off < 1024; off <<= 1) {
        int v = (t >= off) ? s[t - off] : 0;
        __syncthreads();
        s[t] += v;
        __syncthreads();
    }
    int run = s[t] - sum;                    // exclusive prefix
    #pragma unroll
    for (int j = 0; j < C; j++) {
        int idx = base + j;
        if (idx < NNODES) {
            g_row[idx] = run;
            g_off[idx] = run;
            run += g_hist[idx];
        }
    }
    if (t == 1023) g_row[NNODES] = NEDGES;
}
__global__ void csr_scatter(const int* __restrict__ edges) {
    int i = blockIdx.x * 256 + threadIdx.x;
    if (i < NEDGES) {
        int d = edges[2 * i + 1];
        int p = atomicAdd(&g_off[d], 1);
        g_perm[p] = i;
    }
}

// ---------------------------------------------------------------------------
// Kernel: scalar_output = silu(x @ W1 + b1) @ W2 + b2 -> g_so
// ---------------------------------------------------------------------------
#define NB 64

__global__ void __launch_bounds__(256) node_mlp(
    const float4* __restrict__ nss4,
    const float* __restrict__ W1, const float* __restrict__ b1,
    const float* __restrict__ W2, const float* __restrict__ b2)
{
    extern __shared__ float sm[];
    float* sW = sm;              // 16384 floats
    float* sX = sm + 16384;      // 8192
    float* sH = sX + 8192;       // 8192

    const int tid = threadIdx.x;
    const int n0 = blockIdx.x * NB;

    for (int i = tid; i < NB * 32; i += 256) {
        int n = n0 + (i >> 5);
        ((float4*)sX)[i] = (n < NNODES) ? nss4[(size_t)n * 32 + (i & 31)]
                                        : make_float4(0.f, 0.f, 0.f, 0.f);
    }
    for (int i = tid; i < 4096; i += 256)
        ((float4*)sW)[i] = ((const float4*)W1)[i];
    __syncthreads();

    const int tx = tid & 31, ty = tid >> 5;
    const int c0 = tx * 4;

    float4 acc[8];

    #pragma unroll
    for (int i = 0; i < 8; i++) acc[i] = make_float4(0.f, 0.f, 0.f, 0.f);
    #pragma unroll 8
    for (int k = 0; k < 128; k += 4) {
        const float4 w0 = *(const float4*)&sW[(k + 0) * 128 + c0];
        const float4 w1 = *(const float4*)&sW[(k + 1) * 128 + c0];
        const float4 w2 = *(const float4*)&sW[(k + 2) * 128 + c0];
        const float4 w3 = *(const float4*)&sW[(k + 3) * 128 + c0];
        #pragma unroll
        for (int i = 0; i < 8; i++) {
            const int ln = ty * 8 + i;
            const float4 xv = *(const float4*)&sX[ln * 128 + k];
            acc[i] = f4_fma_s(xv.x, w0, acc[i]);
            acc[i] = f4_fma_s(xv.y, w1, acc[i]);
            acc[i] = f4_fma_s(xv.z, w2, acc[i]);
            acc[i] = f4_fma_s(xv.w, w3, acc[i]);
        }
    }
    {
        const float4 bb = __ldg((const float4*)&b1[c0]);
        #pragma unroll
        for (int i = 0; i < 8; i++) {
            const int ln = ty * 8 + i;
            float4 h = make_float4(acc[i].x + bb.x, acc[i].y + bb.y,
                                   acc[i].z + bb.z, acc[i].w + bb.w);
            h.x = h.x / (1.f + __expf(-h.x));
            h.y = h.y / (1.f + __expf(-h.y));
            h.z = h.z / (1.f + __expf(-h.z));
            h.w = h.w / (1.f + __expf(-h.w));
            *(float4*)&sH[ln * 128 + c0] = h;
        }
    }

    for (int t = 0; t < 3; t++) {
        __syncthreads();
        for (int i = tid; i < 4096; i += 256) {
            int k = i >> 5, jj = i & 31;
            ((float4*)sW)[i] = *(const float4*)&W2[(size_t)k * 384 + t * 128 + jj * 4];
        }
        __syncthreads();
        #pragma unroll
        for (int i = 0; i < 8; i++) acc[i] = make_float4(0.f, 0.f, 0.f, 0.f);
        #pragma unroll 8
        for (int k = 0; k < 128; k += 4) {
            const float4 w0 = *(const float4*)&sW[(k + 0) * 128 + c0];
            const float4 w1 = *(const float4*)&sW[(k + 1) * 128 + c0];
            const float4 w2 = *(const float4*)&sW[(k + 2) * 128 + c0];
            const float4 w3 = *(const float4*)&sW[(k + 3) * 128 + c0];
            #pragma unroll
            for (int i = 0; i < 8; i++) {
                const int ln = ty * 8 + i;
                const float4 xv = *(const float4*)&sH[ln * 128 + k];
                acc[i] = f4_fma_s(xv.x, w0, acc[i]);
                acc[i] = f4_fma_s(xv.y, w1, acc[i]);
                acc[i] = f4_fma_s(xv.z, w2, acc[i]);
                acc[i] = f4_fma_s(xv.w, w3, acc[i]);
            }
        }
        const float4 bb = __ldg((const float4*)&b2[t * 128 + c0]);
        #pragma unroll
        for (int i = 0; i < 8; i++) {
            const int ln = ty * 8 + i;
            const int n = n0 + ln;
            if (n < NNODES) {
                float4 r = make_float4(acc[i].x + bb.x, acc[i].y + bb.y,
                                       acc[i].z + bb.z, acc[i].w + bb.w);
                *(float4*)&g_so[(size_t)n * 384 + t * 128 + c0] = r;
            }
        }
    }
}

// ---------------------------------------------------------------------------
// Node-centric gather kernel: one warp per dst node, 2 edges per iteration.
// No atomics: accumulate in registers, single coalesced write at the end.
// ---------------------------------------------------------------------------
__global__ void __launch_bounds__(256) node_gather(
    const float* __restrict__ nss, const float* __restrict__ nsv,
    const float* __restrict__ edge_state, const float* __restrict__ edge_vector,
    const float* __restrict__ edge_distance, const int* __restrict__ edges,
    const float* __restrict__ Wf, const float* __restrict__ bf,
    float* __restrict__ out)
{
    __shared__ __align__(16) float sWf[ESZ * 384];
    __shared__ __align__(16) float sbf[384];
    __shared__ __align__(16) float sES[8][2 * ESZ];

    const int tid = threadIdx.x;
    for (int i = tid; i < ESZ * 384 / 4; i += 256)
        ((float4*)sWf)[i] = ((const float4*)Wf)[i];
    for (int i = tid; i < 96; i += 256)
        ((float4*)sbf)[i] = ((const float4*)bf)[i];
    __syncthreads();

    const int lane = tid & 31;
    const int warp = tid >> 5;
    const int c0   = lane * 4;
    float* myES = sES[warp];

    const ulonglong2 bS = *(const ulonglong2*)&sbf[c0];
    const ulonglong2 bE = *(const ulonglong2*)&sbf[128 + c0];
    const ulonglong2 bN = *(const ulonglong2*)&sbf[256 + c0];

    float* __restrict__ outS = out;
    float* __restrict__ outV = out + (size_t)NNODES * NSZ;

    for (int n = blockIdx.x * 8 + warp; n < NNODES; n += gridDim.x * 8) {
        // accumulators initialized with the node's own state (the "+ x" term)
        float4 aS  = __ldg((const float4*)&nss[(size_t)n * NSZ + c0]);
        float4 aV0 = __ldg((const float4*)&nsv[(size_t)n * 384 + c0]);
        float4 aV1 = __ldg((const float4*)&nsv[(size_t)n * 384 + 128 + c0]);
        float4 aV2 = __ldg((const float4*)&nsv[(size_t)n * 384 + 256 + c0]);

        const int beg = g_row[n], end = g_row[n + 1];

        for (int i = beg; i < end; i += 2) {
            const bool hasB = (i + 1 < end);
            const int iB = hasB ? (i + 1) : i;
            const int edA = __ldg(&g_perm[i]);
            const int edB = __ldg(&g_perm[iB]);

            // stage edge_state rows for both edges into per-warp smem
            __syncwarp();
            if (lane < 10) {
                int e = lane / 5, c = lane % 5;
                int ed = e ? edB : edA;
                *(float4*)&myES[e * ESZ + c * 4] =
                    __ldg((const float4*)&edge_state[(size_t)ed * ESZ] + c);
            }
            __syncwarp();

            // per-edge meta (warp-uniform loads)
            const int srcA = __ldg(&edges[2 * edA]);
            const int srcB = __ldg(&edges[2 * edB]);

            const float dA = __ldg(&edge_distance[edA]);
            const float dB = __ldg(&edge_distance[edB]);
            float cuA = (dA < CUTF)
                ? 0.5f * (__cosf(3.14159265358979f * dA * (1.0f / CUTF)) + 1.0f) : 0.f;
            float cuB = (dB < CUTF)
                ? 0.5f * (__cosf(3.14159265358979f * dB * (1.0f / CUTF)) + 1.0f) : 0.f;
            if (!hasB) cuB = 0.f;   // duplicate edge contributes nothing

            const float va0 = __ldg(&edge_vector[3 * edA]);
            const float va1 = __ldg(&edge_vector[3 * edA + 1]);
            const float va2 = __ldg(&edge_vector[3 * edA + 2]);
            const float ia  = 1.0f / fmaxf(sqrtf(va0*va0 + va1*va1 + va2*va2), 1e-12f);
            const float eA0 = va0 * ia, eA1 = va1 * ia, eA2 = va2 * ia;

            const float vb0 = __ldg(&edge_vector[3 * edB]);
            const float vb1 = __ldg(&edge_vector[3 * edB + 1]);
            const float vb2 = __ldg(&edge_vector[3 * edB + 2]);
            const float ib  = 1.0f / fmaxf(sqrtf(vb0*vb0 + vb1*vb1 + vb2*vb2), 1e-12f);
            const float eB0 = vb0 * ib, eB1 = vb1 * ib, eB2 = vb2 * ib;

            // filter GEMM for both edges, sharing the W smem loads
            u64 fA[6], fB[6];
            fA[0] = bS.x; fA[1] = bS.y; fA[2] = bE.x;
            fA[3] = bE.y; fA[4] = bN.x; fA[5] = bN.y;
            fB[0] = bS.x; fB[1] = bS.y; fB[2] = bE.x;
            fB[3] = bE.y; fB[4] = bN.x; fB[5] = bN.y;
            #pragma unroll
            for (int k = 0; k < ESZ; k++) {
                const ulonglong2 wS = *(const ulonglong2*)&sWf[k * 384 + c0];
                const ulonglong2 wE = *(const ulonglong2*)&sWf[k * 384 + 128 + c0];
                const ulonglong2 wN = *(const ulonglong2*)&sWf[k * 384 + 256 + c0];
                const u64 sA = pack2(myES[k]);
                const u64 sB2 = pack2(myES[ESZ + k]);
                fma2(fA[0], sA, wS.x);  fma2(fA[1], sA, wS.y);
                fma2(fA[2], sA, wE.x);  fma2(fA[3], sA, wE.y);
                fma2(fA[4], sA, wN.x);  fma2(fA[5], sA, wN.y);
                fma2(fB[0], sB2, wS.x); fma2(fB[1], sB2, wS.y);
                fma2(fB[2], sB2, wE.x); fma2(fB[3], sB2, wE.y);
                fma2(fB[4], sB2, wN.x); fma2(fB[5], sB2, wN.y);
            }

            // --- edge A ---
            {
                float2 p0 = unpack2(fA[0]), p1 = unpack2(fA[1]);
                float2 p2 = unpack2(fA[2]), p3 = unpack2(fA[3]);
                float2 p4 = unpack2(fA[4]), p5 = unpack2(fA[5]);
                const float4 fSV = make_float4(p0.x*cuA, p0.y*cuA, p1.x*cuA, p1.y*cuA);
                const float4 fEV = make_float4(p2.x*cuA, p2.y*cuA, p3.x*cuA, p3.y*cuA);
                const float4 fNS = make_float4(p4.x*cuA, p4.y*cuA, p5.x*cuA, p5.y*cuA);

                const float* so = &g_so[(size_t)srcA * 384];
                const float4 foSV = f4_mul(fSV, *(const float4*)&so[c0]);
                const float4 foEV = f4_mul(fEV, *(const float4*)&so[128 + c0]);
                const float4 foNS = f4_mul(fNS, *(const float4*)&so[256 + c0]);

                const float4 xs = __ldg((const float4*)&nss[(size_t)srcA * NSZ + c0]);
                f4_acc_mul(aS, xs, foNS);

                const float* nv = &nsv[(size_t)srcA * 384];
                const float4 xv0 = __ldg((const float4*)&nv[c0]);
                const float4 xv1 = __ldg((const float4*)&nv[128 + c0]);
                const float4 xv2 = __ldg((const float4*)&nv[256 + c0]);
                f4_acc_mul(aV0, xv0, foSV); f4_acc_s(aV0, eA0, foEV);
                f4_acc_mul(aV1, xv1, foSV); f4_acc_s(aV1, eA1, foEV);
                f4_acc_mul(aV2, xv2, foSV); f4_acc_s(aV2, eA2, foEV);
            }
            // --- edge B ---
            {
                float2 p0 = unpack2(fB[0]), p1 = unpack2(fB[1]);
                float2 p2 = unpack2(fB[2]), p3 = unpack2(fB[3]);
                float2 p4 = unpack2(fB[4]), p5 = unpack2(fB[5]);
                const float4 fSV = make_float4(p0.x*cuB, p0.y*cuB, p1.x*cuB, p1.y*cuB);
                const float4 fEV = make_float4(p2.x*cuB, p2.y*cuB, p3.x*cuB, p3.y*cuB);
                const float4 fNS = make_float4(p4.x*cuB, p4.y*cuB, p5.x*cuB, p5.y*cuB);

                const float* so = &g_so[(size_t)srcB * 384];
                const float4 foSV = f4_mul(fSV, *(const float4*)&so[c0]);
                const float4 foEV = f4_mul(fEV, *(const float4*)&so[128 + c0]);
                const float4 foNS = f4_mul(fNS, *(const float4*)&so[256 + c0]);

                const float4 xs = __ldg((const float4*)&nss[(size_t)srcB * NSZ + c0]);
                f4_acc_mul(aS, xs, foNS);

                const float* nv = &nsv[(size_t)srcB * 384];
                const float4 xv0 = __ldg((const float4*)&nv[c0]);
                const float4 xv1 = __ldg((const float4*)&nv[128 + c0]);
                const float4 xv2 = __ldg((const float4*)&nv[256 + c0]);
                f4_acc_mul(aV0, xv0, foSV); f4_acc_s(aV0, eB0, foEV);
                f4_acc_mul(aV1, xv1, foSV); f4_acc_s(aV1, eB1, foEV);
                f4_acc_mul(aV2, xv2, foSV); f4_acc_s(aV2, eB2, foEV);
            }
        }

        // single coalesced write-out
        *(float4*)&outS[(size_t)n * NSZ + c0] = aS;
        float* ov = &outV[(size_t)n * 384];
        *(float4*)&ov[c0]       = aV0;
        *(float4*)&ov[128 + c0] = aV1;
        *(float4*)&ov[256 + c0] = aV2;
    }
}

// ---------------------------------------------------------------------------
extern "C" void kernel_launch(void* const* d_in, const int* in_sizes, int n_in,
                              void* d_out, int out_size)
{
    const float* nss           = (const float*)d_in[0];
    const float* nsv           = (const float*)d_in[1];
    const float* edge_state    = (const float*)d_in[2];
    const float* edge_vector   = (const float*)d_in[3];
    const float* edge_distance = (const float*)d_in[4];
    const int*   edges         = (const int*)d_in[5];
    const float* W_filter      = (const float*)d_in[6];
    const float* b_filter      = (const float*)d_in[7];
    const float* W1            = (const float*)d_in[8];
    const float* b1            = (const float*)d_in[9];
    const float* W2            = (const float*)d_in[10];
    const float* b2            = (const float*)d_in[11];
    float* out = (float*)d_out;

    // CSR build (independent of node MLP)
    csr_zero<<<(NNODES + 256) / 256, 256>>>();
    csr_hist<<<(NEDGES + 255) / 256, 256>>>(edges);
    csr_scan<<<1, 1024>>>();
    csr_scatter<<<(NEDGES + 255) / 256, 256>>>(edges);

    const int smem1 = (16384 + 2 * NB * 128) * sizeof(float);  // 128 KB
    cudaFuncSetAttribute(node_mlp, cudaFuncAttributeMaxDynamicSharedMemorySize, smem1);
    node_mlp<<<(NNODES + NB - 1) / NB, 256, smem1>>>(
        (const float4*)nss, W1, b1, W2, b2);

    node_gather<<<2500, 256>>>(nss, nsv, edge_state, edge_vector, edge_distance,
                               edges, W_filter, b_filter, out);
}

// round 4
// speedup vs baseline: 1.1668x; 1.1668x over previous
#include <cuda_runtime.h>
#include <math.h>

#define NNODES 20000
#define NEDGES 640000
#define NSZ 128
#define ESZ 20
#define CUTF 5.0f

// scratch
__device__ float g_so[NNODES * 384];
__device__ int g_hist[NNODES + 1];
__device__ int g_row[NNODES + 1];
__device__ int g_off[NNODES];
__device__ int g_dst[NEDGES];
__device__ float4 g_meta[NEDGES];        // (en0, en1, en2, cutoff)
__device__ float4 g_esr4[NEDGES * 5];    // edge_state reordered to CSR slots

typedef unsigned long long u64;

// ---------------------------------------------------------------------------
__device__ __forceinline__ void fma2(u64& d, u64 a, u64 b) {
    asm("fma.rn.f32x2 %0, %1, %2, %0;" : "+l"(d) : "l"(a), "l"(b));
}
__device__ __forceinline__ u64 pack2(float x) {
    u64 r; asm("mov.b64 %0, {%1, %1};" : "=l"(r) : "f"(x)); return r;
}
__device__ __forceinline__ float2 unpack2(u64 a) {
    float2 f; asm("mov.b64 {%0, %1}, %2;" : "=f"(f.x), "=f"(f.y) : "l"(a));
    return f;
}
__device__ __forceinline__ float4 f4_mul(float4 a, float4 b) {
    return make_float4(a.x*b.x, a.y*b.y, a.z*b.z, a.w*b.w);
}
// xv * g + s * f
__device__ __forceinline__ float4 f4_msg(float4 xv, float4 g, float s, float4 f) {
    return make_float4(fmaf(xv.x, g.x, s*f.x), fmaf(xv.y, g.y, s*f.y),
                       fmaf(xv.z, g.z, s*f.z), fmaf(xv.w, g.w, s*f.w));
}
__device__ __forceinline__ void red4(float* p, float4 v) {
    asm volatile("red.global.add.v4.f32 [%0], {%1, %2, %3, %4};"
                 :: "l"(p), "f"(v.x), "f"(v.y), "f"(v.z), "f"(v.w) : "memory");
}

// ---------------------------------------------------------------------------
// CSR build (keyed by src) + edge-data pre-gather into CSR order
// ---------------------------------------------------------------------------
__global__ void csr_zero() {
    int i = blockIdx.x * 256 + threadIdx.x;
    if (i <= NNODES) g_hist[i] = 0;
}
__global__ void csr_hist(const int* __restrict__ edges) {
    int i = blockIdx.x * 256 + threadIdx.x;
    if (i < NEDGES) atomicAdd(&g_hist[edges[2 * i]], 1);
}
__global__ void __launch_bounds__(1024) csr_scan() {
    __shared__ int s[1024];
    const int t = threadIdx.x;
    const int C = 20;
    const int base = t * C;
    int sum = 0;
    #pragma unroll
    for (int j = 0; j < C; j++) {
        int idx = base + j;
        if (idx < NNODES) sum += g_hist[idx];
    }
    s[t] = sum;
    __syncthreads();
    for (int off = 1; off < 1024; off <<= 1) {
        int v = (t >= off) ? s[t - off] : 0;
        __syncthreads();
        s[t] += v;
        __syncthreads();
    }
    int run = s[t] - sum;
    #pragma unroll
    for (int j = 0; j < C; j++) {
        int idx = base + j;
        if (idx < NNODES) {
            g_row[idx] = run;
            g_off[idx] = run;
            run += g_hist[idx];
        }
    }
    if (t == 1023) g_row[NNODES] = NEDGES;
}
__global__ void csr_scatter(const int* __restrict__ edges,
                            const float* __restrict__ edge_vector,
                            const float* __restrict__ edge_distance,
                            const float4* __restrict__ edge_state4)
{
    int i = blockIdx.x * 256 + threadIdx.x;
    if (i >= NEDGES) return;
    const int s = edges[2 * i];
    const int d = edges[2 * i + 1];
    const int p = atomicAdd(&g_off[s], 1);
    g_dst[p] = d;

    const float v0 = __ldg(&edge_vector[3 * i]);
    const float v1 = __ldg(&edge_vector[3 * i + 1]);
    const float v2 = __ldg(&edge_vector[3 * i + 2]);
    const float inv = 1.0f / fmaxf(sqrtf(v0*v0 + v1*v1 + v2*v2), 1e-12f);
    const float dist = __ldg(&edge_distance[i]);
    const float cu = (dist < CUTF)
        ? 0.5f * (__cosf(3.14159265358979f * dist * (1.0f / CUTF)) + 1.0f) : 0.0f;
    g_meta[p] = make_float4(v0 * inv, v1 * inv, v2 * inv, cu);

    #pragma unroll
    for (int c = 0; c < 5; c++)
        g_esr4[(size_t)p * 5 + c] = __ldg(&edge_state4[(size_t)i * 5 + c]);
}

// ---------------------------------------------------------------------------
// Kernel: scalar_output = silu(x @ W1 + b1) @ W2 + b2 -> g_so  (f32x2 FMA)
//         + copies this block's slice of [nss | nsv] into out (init fold)
// ---------------------------------------------------------------------------
#define NB 64

__global__ void __launch_bounds__(256) node_mlp(
    const float4* __restrict__ nss4, const float4* __restrict__ nsv4,
    const float* __restrict__ W1, const float* __restrict__ b1,
    const float* __restrict__ W2, const float* __restrict__ b2,
    float4* __restrict__ out)
{
    extern __shared__ float sm[];
    float* sW = sm;              // 16384 floats
    float* sX = sm + 16384;      // 8192
    float* sH = sX + 8192;       // 8192

    const int tid = threadIdx.x;
    const int n0 = blockIdx.x * NB;

    // fold: out base copy
    {
        const float4* nssb = nss4 + (size_t)n0 * 32;
        float4* outS = out + (size_t)n0 * 32;
        for (int i = tid; i < NB * 32; i += 256)
            if (n0 + (i >> 5) < NNODES) outS[i] = nssb[i];
        const float4* nsvb = nsv4 + (size_t)n0 * 96;
        float4* outV = out + (size_t)NNODES * 32 + (size_t)n0 * 96;
        for (int i = tid; i < NB * 96; i += 256)
            if (n0 + i / 96 < NNODES) outV[i] = nsvb[i];
    }

    for (int i = tid; i < NB * 32; i += 256) {
        int n = n0 + (i >> 5);
        ((float4*)sX)[i] = (n < NNODES) ? nss4[(size_t)n * 32 + (i & 31)]
                                        : make_float4(0.f, 0.f, 0.f, 0.f);
    }
    for (int i = tid; i < 4096; i += 256)
        ((float4*)sW)[i] = ((const float4*)W1)[i];
    __syncthreads();

    const int tx = tid & 31, ty = tid >> 5;
    const int c0 = tx * 4;

    u64 acc[8][2];

    // phase 1
    #pragma unroll
    for (int i = 0; i < 8; i++) { acc[i][0] = 0ull; acc[i][1] = 0ull; }
    #pragma unroll 8
    for (int k = 0; k < 128; k += 4) {
        const ulonglong2 w0 = *(const ulonglong2*)&sW[(k + 0) * 128 + c0];
        const ulonglong2 w1 = *(const ulonglong2*)&sW[(k + 1) * 128 + c0];
        const ulonglong2 w2 = *(const ulonglong2*)&sW[(k + 2) * 128 + c0];
        const ulonglong2 w3 = *(const ulonglong2*)&sW[(k + 3) * 128 + c0];
        #pragma unroll
        for (int i = 0; i < 8; i++) {
            const int ln = ty * 8 + i;
            const float4 xv = *(const float4*)&sX[ln * 128 + k];
            const u64 x0 = pack2(xv.x), x1 = pack2(xv.y);
            const u64 x2 = pack2(xv.z), x3 = pack2(xv.w);
            fma2(acc[i][0], x0, w0.x); fma2(acc[i][1], x0, w0.y);
            fma2(acc[i][0], x1, w1.x); fma2(acc[i][1], x1, w1.y);
            fma2(acc[i][0], x2, w2.x); fma2(acc[i][1], x2, w2.y);
            fma2(acc[i][0], x3, w3.x); fma2(acc[i][1], x3, w3.y);
        }
    }
    {
        const float4 bb = __ldg((const float4*)&b1[c0]);
        #pragma unroll
        for (int i = 0; i < 8; i++) {
            const int ln = ty * 8 + i;
            const float2 lo = unpack2(acc[i][0]);
            const float2 hi = unpack2(acc[i][1]);
            float4 h = make_float4(lo.x + bb.x, lo.y + bb.y, hi.x + bb.z, hi.y + bb.w);
            h.x = h.x / (1.f + __expf(-h.x));
            h.y = h.y / (1.f + __expf(-h.y));
            h.z = h.z / (1.f + __expf(-h.z));
            h.w = h.w / (1.f + __expf(-h.w));
            *(float4*)&sH[ln * 128 + c0] = h;
        }
    }

    // phase 2: 3 output tiles
    for (int t = 0; t < 3; t++) {
        __syncthreads();
        for (int i = tid; i < 4096; i += 256) {
            int k = i >> 5, jj = i & 31;
            ((float4*)sW)[i] = *(const float4*)&W2[(size_t)k * 384 + t * 128 + jj * 4];
        }
        __syncthreads();
        #pragma unroll
        for (int i = 0; i < 8; i++) { acc[i][0] = 0ull; acc[i][1] = 0ull; }
        #pragma unroll 8
        for (int k = 0; k < 128; k += 4) {
            const ulonglong2 w0 = *(const ulonglong2*)&sW[(k + 0) * 128 + c0];
            const ulonglong2 w1 = *(const ulonglong2*)&sW[(k + 1) * 128 + c0];
            const ulonglong2 w2 = *(const ulonglong2*)&sW[(k + 2) * 128 + c0];
            const ulonglong2 w3 = *(const ulonglong2*)&sW[(k + 3) * 128 + c0];
            #pragma unroll
            for (int i = 0; i < 8; i++) {
                const int ln = ty * 8 + i;
                const float4 xv = *(const float4*)&sH[ln * 128 + k];
                const u64 x0 = pack2(xv.x), x1 = pack2(xv.y);
                const u64 x2 = pack2(xv.z), x3 = pack2(xv.w);
                fma2(acc[i][0], x0, w0.x); fma2(acc[i][1], x0, w0.y);
                fma2(acc[i][0], x1, w1.x); fma2(acc[i][1], x1, w1.y);
                fma2(acc[i][0], x2, w2.x); fma2(acc[i][1], x2, w2.y);
                fma2(acc[i][0], x3, w3.x); fma2(acc[i][1], x3, w3.y);
            }
        }
        const float4 bb = __ldg((const float4*)&b2[t * 128 + c0]);
        #pragma unroll
        for (int i = 0; i < 8; i++) {
            const int ln = ty * 8 + i;
            const int n = n0 + ln;
            if (n < NNODES) {
                const float2 lo = unpack2(acc[i][0]);
                const float2 hi = unpack2(acc[i][1]);
                *(float4*)&g_so[(size_t)n * 384 + t * 128 + c0] =
                    make_float4(lo.x + bb.x, lo.y + bb.y, hi.x + bb.z, hi.y + bb.w);
            }
        }
    }
}

// ---------------------------------------------------------------------------
// src-centric gather/scatter: warp per src node; src payload hoisted into
// registers and reused across all outgoing edges. Edges read in CSR order
// (coalesced pre-gathered arrays). Messages scattered with red.global.v4.
// ---------------------------------------------------------------------------
#define EPW 4

__global__ void __launch_bounds__(256) src_gather(
    const float* __restrict__ nss, const float* __restrict__ nsv,
    const float* __restrict__ Wf, const float* __restrict__ bf,
    float* __restrict__ out)
{
    __shared__ __align__(16) float sWf[ESZ * 384];
    __shared__ __align__(16) float sbf[384];
    __shared__ __align__(16) float sES[8][EPW * ESZ];

    const int tid = threadIdx.x;
    for (int i = tid; i < ESZ * 384 / 4; i += 256)
        ((float4*)sWf)[i] = ((const float4*)Wf)[i];
    for (int i = tid; i < 96; i += 256)
        ((float4*)sbf)[i] = ((const float4*)bf)[i];
    __syncthreads();

    const int lane = tid & 31;
    const int warp = tid >> 5;
    const int c0   = lane * 4;
    float* myES = sES[warp];

    const ulonglong2 bS = *(const ulonglong2*)&sbf[c0];
    const ulonglong2 bE = *(const ulonglong2*)&sbf[128 + c0];
    const ulonglong2 bN = *(const ulonglong2*)&sbf[256 + c0];

    float* __restrict__ outS = out;
    float* __restrict__ outV = out + (size_t)NNODES * NSZ;

    for (int n = blockIdx.x * 8 + warp; n < NNODES; n += gridDim.x * 8) {
        const int beg = g_row[n], end = g_row[n + 1];
        if (beg == end) continue;

        // hoist src payload (reused for every outgoing edge)
        const float4 soSV = __ldg((const float4*)&g_so[(size_t)n * 384 + c0]);
        const float4 soEV = __ldg((const float4*)&g_so[(size_t)n * 384 + 128 + c0]);
        const float4 soNS = __ldg((const float4*)&g_so[(size_t)n * 384 + 256 + c0]);
        const float4 xs   = __ldg((const float4*)&nss[(size_t)n * NSZ + c0]);
        const float4 xv0  = __ldg((const float4*)&nsv[(size_t)n * 384 + c0]);
        const float4 xv1  = __ldg((const float4*)&nsv[(size_t)n * 384 + 128 + c0]);
        const float4 xv2  = __ldg((const float4*)&nsv[(size_t)n * 384 + 256 + c0]);

        for (int g = beg; g < end; g += EPW) {
            // stage edge_state for up to EPW edges (contiguous in CSR order)
            __syncwarp();
            if (lane < EPW * 5) {
                const int slot = min(g + lane / 5, end - 1);
                *(float4*)&myES[(lane / 5) * ESZ + (lane % 5) * 4] =
                    __ldg(&g_esr4[(size_t)slot * 5 + (lane % 5)]);
            }
            __syncwarp();

            float4 mt[EPW];
            int dstE[EPW];
            float cu[EPW];
            #pragma unroll
            for (int e = 0; e < EPW; e++) {
                const int slot = min(g + e, end - 1);
                mt[e]   = __ldg(&g_meta[slot]);
                dstE[e] = __ldg(&g_dst[slot]);
                cu[e]   = (g + e < end) ? mt[e].w : 0.0f;
            }

            // filter GEMM for EPW edges (shared W smem loads, f32x2)
            u64 fa[EPW][6];
            #pragma unroll
            for (int e = 0; e < EPW; e++) {
                fa[e][0] = bS.x; fa[e][1] = bS.y;
                fa[e][2] = bE.x; fa[e][3] = bE.y;
                fa[e][4] = bN.x; fa[e][5] = bN.y;
            }
            #pragma unroll
            for (int k = 0; k < ESZ; k++) {
                const ulonglong2 wS = *(const ulonglong2*)&sWf[k * 384 + c0];
                const ulonglong2 wE = *(const ulonglong2*)&sWf[k * 384 + 128 + c0];
                const ulonglong2 wN = *(const ulonglong2*)&sWf[k * 384 + 256 + c0];
                #pragma unroll
                for (int e = 0; e < EPW; e++) {
                    const u64 s2 = pack2(myES[e * ESZ + k]);
                    fma2(fa[e][0], s2, wS.x); fma2(fa[e][1], s2, wS.y);
                    fma2(fa[e][2], s2, wE.x); fma2(fa[e][3], s2, wE.y);
                    fma2(fa[e][4], s2, wN.x); fma2(fa[e][5], s2, wN.y);
                }
            }

            // messages + scatter
            #pragma unroll
            for (int e = 0; e < EPW; e++) {
                const float c = cu[e];
                float2 p0 = unpack2(fa[e][0]), p1 = unpack2(fa[e][1]);
                float2 p2 = unpack2(fa[e][2]), p3 = unpack2(fa[e][3]);
                float2 p4 = unpack2(fa[e][4]), p5 = unpack2(fa[e][5]);
                const float4 fSV = make_float4(p0.x*c, p0.y*c, p1.x*c, p1.y*c);
                const float4 fEV = make_float4(p2.x*c, p2.y*c, p3.x*c, p3.y*c);
                const float4 fNS = make_float4(p4.x*c, p4.y*c, p5.x*c, p5.y*c);

                const float4 foSV = f4_mul(fSV, soSV);
                const float4 foEV = f4_mul(fEV, soEV);
                const float4 foNS = f4_mul(fNS, soNS);

                const int dst = dstE[e];
                if (c != 0.0f || (g + e < end)) {
                    red4(&outS[(size_t)dst * NSZ + c0], f4_mul(xs, foNS));
                    float* ov = &outV[(size_t)dst * 384];
                    red4(&ov[c0],       f4_msg(xv0, foSV, mt[e].x, foEV));
                    red4(&ov[128 + c0], f4_msg(xv1, foSV, mt[e].y, foEV));
                    red4(&ov[256 + c0], f4_msg(xv2, foSV, mt[e].z, foEV));
                }
            }
        }
    }
}

// ---------------------------------------------------------------------------
extern "C" void kernel_launch(void* const* d_in, const int* in_sizes, int n_in,
                              void* d_out, int out_size)
{
    const float* nss           = (const float*)d_in[0];
    const float* nsv           = (const float*)d_in[1];
    const float* edge_state    = (const float*)d_in[2];
    const float* edge_vector   = (const float*)d_in[3];
    const float* edge_distance = (const float*)d_in[4];
    const int*   edges         = (const int*)d_in[5];
    const float* W_filter      = (const float*)d_in[6];
    const float* b_filter      = (const float*)d_in[7];
    const float* W1            = (const float*)d_in[8];
    const float* b1            = (const float*)d_in[9];
    const float* W2            = (const float*)d_in[10];
    const float* b2            = (const float*)d_in[11];
    float* out = (float*)d_out;

    csr_zero<<<(NNODES + 256) / 256, 256>>>();
    csr_hist<<<(NEDGES + 255) / 256, 256>>>(edges);
    csr_scan<<<1, 1024>>>();
    csr_scatter<<<(NEDGES + 255) / 256, 256>>>(edges, edge_vector, edge_distance,
                                               (const float4*)edge_state);

    const int smem1 = (16384 + 2 * NB * 128) * sizeof(float);  // 128 KB
    cudaFuncSetAttribute(node_mlp, cudaFuncAttributeMaxDynamicSharedMemorySize, smem1);
    node_mlp<<<(NNODES + NB - 1) / NB, 256, smem1>>>(
        (const float4*)nss, (const float4*)nsv, W1, b1, W2, b2, (float4*)out);

    src_gather<<<2500, 256>>>(nss, nsv, W_filter, b_filter, out);
}